// round 4
// baseline (speedup 1.0000x reference)
#include <cuda_runtime.h>

#define L      512
#define NT     256
#define NSIG   4096
#define NTOT   (32*512*128)
// pad every 8 floats: conflict-free Stockham radix-8 stores (9j+p, gcd(9,32)=1)
#define IDX(c) ((c) + ((c) >> 3))

__device__ float g_omega[NSIG * 2];
__device__ int   g_swap[32];

__device__ __forceinline__ float warpsum(float v) {
#pragma unroll
    for (int o = 16; o; o >>= 1) v += __shfl_xor_sync(0xffffffffu, v, o);
    return v;
}

struct C2 { float x, y; };
__device__ __forceinline__ C2 cadd(C2 a, C2 b) { return {a.x + b.x, a.y + b.y}; }
__device__ __forceinline__ C2 csub(C2 a, C2 b) { return {a.x - b.x, a.y - b.y}; }
__device__ __forceinline__ C2 cmul(C2 a, C2 b) {
    return {a.x * b.x - a.y * b.y, a.x * b.y + a.y * b.x};
}
__device__ __forceinline__ C2 cmuli(C2 a, float sgn) { return {-sgn * a.y, sgn * a.x}; }

// 512-pt Stockham radix-8 FFT, 3 stages. Stage 0 reads the packed input
// W = (Pr - Qi) + i*(Pi + Qr) = P + i*Q. Buffers: S0:(P,Q)->C, S1:C->P, S2:P->C.
// Output in (Cr,Ci). sgn=-1 forward, +1 inverse twiddles; NO 1/N scaling.
// First action is __syncthreads() (covers caller's writes to P/Q).
__device__ void fft512_pack(float* Pr, float* Pi, float* Qr, float* Qi,
                            float* Cr, float* Ci, float sgn, int tid) {
    const float S2 = 0.70710678118654752f;
    __syncthreads();
#pragma unroll
    for (int st = 0; st < 3; st++) {
        if (tid < 64) {
            const int j = (st == 0) ? tid : ((st == 1) ? (tid >> 3) : 0);
            const int k = (st == 0) ? 0   : ((st == 1) ? (tid & 7) : tid);
            const int l = (st == 0) ? 64  : ((st == 1) ? 8 : 1);
            const int m = (st == 0) ? 1   : ((st == 1) ? 8 : 64);
            C2 c[8];
#pragma unroll
            for (int q = 0; q < 8; q++) {
                int idx = IDX(k + m * (j + l * q));
                if (st == 0)      { c[q].x = Pr[idx] - Qi[idx]; c[q].y = Pi[idx] + Qr[idx]; }
                else if (st == 1) { c[q].x = Cr[idx]; c[q].y = Ci[idx]; }
                else              { c[q].x = Pr[idx]; c[q].y = Pi[idx]; }
            }
            C2 t0 = cadd(c[0], c[4]), t1 = csub(c[0], c[4]);
            C2 t2 = cadd(c[2], c[6]), t3 = cmuli(csub(c[2], c[6]), sgn);
            C2 u0 = cadd(c[1], c[5]), u1 = csub(c[1], c[5]);
            C2 u2 = cadd(c[3], c[7]), u3 = cmuli(csub(c[3], c[7]), sgn);
            C2 E0 = cadd(t0, t2), E2 = csub(t0, t2);
            C2 E1 = cadd(t1, t3), E3 = csub(t1, t3);
            C2 O0 = cadd(u0, u2), O2 = csub(u0, u2);
            C2 O1 = cadd(u1, u3), O3 = csub(u1, u3);
            C2 w1c = { S2, sgn * S2};
            C2 w3c = {-S2, sgn * S2};
            C2 o1 = cmul(O1, w1c);
            C2 o2 = cmuli(O2, sgn);
            C2 o3 = cmul(O3, w3c);
            C2 dd[8];
            dd[0] = cadd(E0, O0); dd[4] = csub(E0, O0);
            dd[1] = cadd(E1, o1); dd[5] = csub(E1, o1);
            dd[2] = cadd(E2, o2); dd[6] = csub(E2, o2);
            dd[3] = cadd(E3, o3); dd[7] = csub(E3, o3);
            if (j) {
                float ang = sgn * 6.283185307179586f * (float)j / (float)(8 * l);
                C2 w, wp;
                __sincosf(ang, &wp.y, &wp.x);
                w = wp;
#pragma unroll
                for (int p = 1; p < 8; p++) {
                    dd[p] = cmul(dd[p], w);
                    w = cmul(w, wp);
                }
            }
#pragma unroll
            for (int p = 0; p < 8; p++) {
                int idx = IDX(k + m * (8 * j + p));
                if (st == 1) { Pr[idx] = dd[p].x; Pi[idx] = dd[p].y; }
                else         { Cr[idx] = dd[p].x; Ci[idx] = dd[p].y; }
            }
        }
        __syncthreads();
    }
}

// One CTA = TWO signals (group g = tid>>7). Each 128-thread group keeps its
// signal's spectra register-resident (thread wt owns bins {wt,256-wt,256+wt,512-wt};
// wt==0 owns {0,128,256,384}). The per-iteration real-output ifft of both
// signals is packed into ONE complex FFT: ifft(H_A + i*H_B) = h_A + i*h_B.
__global__ void __launch_bounds__(NT, 3) vmd_main(const float* __restrict__ x,
                                                  float* __restrict__ out) {
    __shared__ float Pr[576], Pi[576], Qr[576], Qi[576], Cr[576], Ci[576];
    __shared__ float red[64];

    const int tid = threadIdx.x;
    const int g = tid >> 7;          // signal group within CTA
    const int wt = tid & 127;        // lane within group
    const int sig = blockIdx.x * 2 + g;
    const int b = sig >> 7, d = sig & 127;
    const float* xp = x + (size_t)b * 65536 + d;

    const bool isT0 = (wt == 0);
    const int tv0 = isT0 ? 0   : wt;
    const int tv1 = isT0 ? 128 : 256 - wt;
    const int tv2 = isT0 ? 256 : 256 + wt;
    const int tv3 = isT0 ? 384 : 512 - wt;
    const int i0 = IDX(tv0), i1 = IDX(tv1), i2 = IDX(tv2), i3 = IDX(tv3);
    const float f0 = (float)tv0 * (1.0f / 512.0f);
    const float f1 = (float)tv1 * (1.0f / 512.0f);
    const float f2 = (float)(tv2 - 512) * (1.0f / 512.0f);
    const float f3 = (float)(tv3 - 512) * (1.0f / 512.0f);

    const float xs0 = xp[(size_t)tv0 * 128];
    const float xs1 = xp[(size_t)tv1 * 128];
    const float xs2 = xp[(size_t)tv2 * 128];
    const float xs3 = xp[(size_t)tv3 * 128];

    // pack forward FFT input: W = x_A + i*x_B
    if (g == 0) {
        Pr[i0] = xs0; Pi[i0] = 0.0f;
        Pr[i1] = xs1; Pi[i1] = 0.0f;
        Pr[i2] = xs2; Pi[i2] = 0.0f;
        Pr[i3] = xs3; Pi[i3] = 0.0f;
    } else {
        Qr[i0] = xs0; Qi[i0] = 0.0f;
        Qr[i1] = xs1; Qi[i1] = 0.0f;
        Qr[i2] = xs2; Qi[i2] = 0.0f;
        Qr[i3] = xs3; Qi[i3] = 0.0f;
    }
    fft512_pack(Pr, Pi, Qr, Qi, Cr, Ci, -1.0f, tid);
    // unpack: Z at own bins; mirrors are thread-local
    float X0r, X0i, X1r, X1i, X2r, X2i, X3r, X3i;
    {
        float Z0r = Cr[i0], Z0i = Ci[i0];
        float Z1r = Cr[i1], Z1i = Ci[i1];
        float Z2r = Cr[i2], Z2i = Ci[i2];
        float Z3r = Cr[i3], Z3i = Ci[i3];
        float m0r = isT0 ? Z0r : Z3r, m0i = isT0 ? Z0i : Z3i;
        float m1r = isT0 ? Z3r : Z2r, m1i = isT0 ? Z3i : Z2i;
        float m2r = isT0 ? Z2r : Z1r, m2i = isT0 ? Z2i : Z1i;
        float m3r = isT0 ? Z1r : Z0r, m3i = isT0 ? Z1i : Z0i;
        if (g == 0) {   // X_A = (Z + conj(Zm))/2
            X0r = 0.5f * (Z0r + m0r); X0i = 0.5f * (Z0i - m0i);
            X1r = 0.5f * (Z1r + m1r); X1i = 0.5f * (Z1i - m1i);
            X2r = 0.5f * (Z2r + m2r); X2i = 0.5f * (Z2i - m2i);
            X3r = 0.5f * (Z3r + m3r); X3i = 0.5f * (Z3i - m3i);
        } else {        // X_B = (Z - conj(Zm))/(2i)
            X0r = 0.5f * (Z0i + m0i); X0i = 0.5f * (m0r - Z0r);
            X1r = 0.5f * (Z1i + m1i); X1i = 0.5f * (m1r - Z1r);
            X2r = 0.5f * (Z2i + m2i); X2i = 0.5f * (m2r - Z2r);
            X3r = 0.5f * (Z3i + m3i); X3i = 0.5f * (m3r - Z3r);
        }
    }

    float u0r0, u0i0, u0r1, u0i1, u0r2, u0i2, u0r3, u0i3;
    float u1r0 = 0.f, u1i0 = 0.f, u1r1 = 0.f, u1i1 = 0.f;
    float u1r2 = 0.f, u1i2 = 0.f, u1r3 = 0.f, u1i3 = 0.f;
    float l0 = 0.f, l1 = 0.f, l2 = 0.f, l3 = 0.f;
    float om0 = 0.0f, om1 = 0.0f;
    const float* hsrc = g ? Ci : Cr;   // packed-ifft real output for this group

    for (int iter = 0; iter < 50; iter++) {
        // ---- Pass A: U0 = (X - Herm(U1) + lam'/2) / (1 + 2a(f-om0)^2)
        float m0r = isT0 ? u1r0 : u1r3, m0i = isT0 ? u1i0 : u1i3;
        float m1r = isT0 ? u1r3 : u1r2, m1i = isT0 ? u1i3 : u1i2;
        float m2r = isT0 ? u1r2 : u1r1, m2i = isT0 ? u1i2 : u1i1;
        float m3r = isT0 ? u1r1 : u1r0, m3i = isT0 ? u1i1 : u1i0;
        float h0r = 0.5f * (u1r0 + m0r), h0i = 0.5f * (u1i0 - m0i);
        float h1r = 0.5f * (u1r1 + m1r), h1i = 0.5f * (u1i1 - m1i);
        float h2r = 0.5f * (u1r2 + m2r), h2i = 0.5f * (u1i2 - m2i);
        float h3r = 0.5f * (u1r3 + m3r), h3i = 0.5f * (u1i3 - m3i);
        float df, q;
        df = f0 - om0; q = __frcp_rn(fmaf(1600.0f * df, df, 1.0f));
        u0r0 = (X0r - h0r + 0.5f * l2) * q; u0i0 = (X0i - h0i) * q;
        df = f1 - om0; q = __frcp_rn(fmaf(1600.0f * df, df, 1.0f));
        u0r1 = (X1r - h1r + 0.5f * l3) * q; u0i1 = (X1i - h1i) * q;
        df = f2 - om0; q = __frcp_rn(fmaf(1600.0f * df, df, 1.0f));
        u0r2 = (X2r - h2r + 0.5f * l0) * q; u0i2 = (X2i - h2i) * q;
        df = f3 - om0; q = __frcp_rn(fmaf(1600.0f * df, df, 1.0f));
        u0r3 = (X3r - h3r + 0.5f * l1) * q; u0i3 = (X3i - h3i) * q;

        // ---- Pass B: h = Herm(U0); omega0 sums; U1 update. Keep h live for Pass C.
        m0r = isT0 ? u0r0 : u0r3; m0i = isT0 ? u0i0 : u0i3;
        m1r = isT0 ? u0r3 : u0r2; m1i = isT0 ? u0i3 : u0i2;
        m2r = isT0 ? u0r2 : u0r1; m2i = isT0 ? u0i2 : u0i1;
        m3r = isT0 ? u0r1 : u0r0; m3i = isT0 ? u0i1 : u0i0;
        h0r = 0.5f * (u0r0 + m0r); h0i = 0.5f * (u0i0 - m0i);
        h1r = 0.5f * (u0r1 + m1r); h1i = 0.5f * (u0i1 - m1i);
        h2r = 0.5f * (u0r2 + m2r); h2i = 0.5f * (u0i2 - m2i);
        h3r = 0.5f * (u0r3 + m3r); h3i = 0.5f * (u0i3 - m3i);
        float p0 = h0r * h0r + h0i * h0i;
        float p1 = h1r * h1r + h1i * h1i;
        float n0 = f0 * p0 + f1 * p1, den0 = p0 + p1;
        df = f0 - om1; q = __frcp_rn(fmaf(1600.0f * df, df, 1.0f));
        u1r0 = (X0r - h0r + 0.5f * l2) * q; u1i0 = (X0i - h0i) * q;
        df = f1 - om1; q = __frcp_rn(fmaf(1600.0f * df, df, 1.0f));
        u1r1 = (X1r - h1r + 0.5f * l3) * q; u1i1 = (X1i - h1i) * q;
        df = f2 - om1; q = __frcp_rn(fmaf(1600.0f * df, df, 1.0f));
        u1r2 = (X2r - h2r + 0.5f * l0) * q; u1i2 = (X2i - h2i) * q;
        df = f3 - om1; q = __frcp_rn(fmaf(1600.0f * df, df, 1.0f));
        u1r3 = (X3r - h3r + 0.5f * l1) * q; u1i3 = (X3i - h3i) * q;

        // ---- Pass C: k = Herm(U1); omega1 sums; scatter H = Herm(U0)+Herm(U1)
        m0r = isT0 ? u1r0 : u1r3; m0i = isT0 ? u1i0 : u1i3;
        m1r = isT0 ? u1r3 : u1r2; m1i = isT0 ? u1i3 : u1i2;
        m2r = isT0 ? u1r2 : u1r1; m2i = isT0 ? u1i2 : u1i1;
        m3r = isT0 ? u1r1 : u1r0; m3i = isT0 ? u1i1 : u1i0;
        float k0r = 0.5f * (u1r0 + m0r), k0i = 0.5f * (u1i0 - m0i);
        float k1r = 0.5f * (u1r1 + m1r), k1i = 0.5f * (u1i1 - m1i);
        float k2r = 0.5f * (u1r2 + m2r), k2i = 0.5f * (u1i2 - m2i);
        float k3r = 0.5f * (u1r3 + m3r), k3i = 0.5f * (u1i3 - m3i);
        p0 = k0r * k0r + k0i * k0i;
        p1 = k1r * k1r + k1i * k1i;
        float n1 = f0 * p0 + f1 * p1, den1 = p0 + p1;

        if (g == 0) {
            Pr[i0] = h0r + k0r; Pi[i0] = h0i + k0i;
            Pr[i1] = h1r + k1r; Pi[i1] = h1i + k1i;
            Pr[i2] = h2r + k2r; Pi[i2] = h2i + k2i;
            Pr[i3] = h3r + k3r; Pi[i3] = h3i + k3i;
        } else {
            Qr[i0] = h0r + k0r; Qi[i0] = h0i + k0i;
            Qr[i1] = h1r + k1r; Qi[i1] = h1i + k1i;
            Qr[i2] = h2r + k2r; Qi[i2] = h2i + k2i;
            Qr[i3] = h3r + k3r; Qi[i3] = h3i + k3i;
        }

        // per-group reduction, parity double-buffered
        n0 = warpsum(n0); den0 = warpsum(den0);
        n1 = warpsum(n1); den1 = warpsum(den1);
        {
            int base = g * 32 + ((iter & 1) << 4);
            int w = (tid >> 5) & 3;
            if ((tid & 31) == 0) {
                red[base + w] = n0;      red[base + 4 + w] = den0;
                red[base + 8 + w] = n1;  red[base + 12 + w] = den1;
            }
        }
        fft512_pack(Pr, Pi, Qr, Qi, Cr, Ci, +1.0f, tid);  // ifft(H_A + i*H_B)
        {
            int base = g * 32 + ((iter & 1) << 4);
            om0 = (red[base + 0] + red[base + 1] + red[base + 2] + red[base + 3]) /
                  (red[base + 4] + red[base + 5] + red[base + 6] + red[base + 7] + 1e-7f);
            om1 = (red[base + 8] + red[base + 9] + red[base + 10] + red[base + 11]) /
                  (red[base + 12] + red[base + 13] + red[base + 14] + red[base + 15] + 1e-7f);
        }
        // lam += tau * (x - h/512);  h for this group = hsrc
        l0 = fmaf(0.001f, xs0 - hsrc[i0] * (1.0f / 512.0f), l0);
        l1 = fmaf(0.001f, xs1 - hsrc[i1] * (1.0f / 512.0f), l1);
        l2 = fmaf(0.001f, xs2 - hsrc[i2] * (1.0f / 512.0f), l2);
        l3 = fmaf(0.001f, xs3 - hsrc[i3] * (1.0f / 512.0f), l3);
    }

    if (wt == 0) {
        g_omega[sig * 2 + 0] = om0;
        g_omega[sig * 2 + 1] = om1;
    }

    // ---- u0 output: pack Herm(U0_A) + i*Herm(U0_B), one ifft
    {
        float m0r = isT0 ? u0r0 : u0r3, m0i = isT0 ? u0i0 : u0i3;
        float m1r = isT0 ? u0r3 : u0r2, m1i = isT0 ? u0i3 : u0i2;
        float m2r = isT0 ? u0r2 : u0r1, m2i = isT0 ? u0i2 : u0i1;
        float m3r = isT0 ? u0r1 : u0r0, m3i = isT0 ? u0i1 : u0i0;
        float H0r = 0.5f * (u0r0 + m0r), H0i = 0.5f * (u0i0 - m0i);
        float H1r = 0.5f * (u0r1 + m1r), H1i = 0.5f * (u0i1 - m1i);
        float H2r = 0.5f * (u0r2 + m2r), H2i = 0.5f * (u0i2 - m2i);
        float H3r = 0.5f * (u0r3 + m3r), H3i = 0.5f * (u0i3 - m3i);
        if (g == 0) {
            Pr[i0] = H0r; Pi[i0] = H0i; Pr[i1] = H1r; Pi[i1] = H1i;
            Pr[i2] = H2r; Pi[i2] = H2i; Pr[i3] = H3r; Pi[i3] = H3i;
        } else {
            Qr[i0] = H0r; Qi[i0] = H0i; Qr[i1] = H1r; Qi[i1] = H1i;
            Qr[i2] = H2r; Qi[i2] = H2i; Qr[i3] = H3r; Qi[i3] = H3i;
        }
    }
    fft512_pack(Pr, Pi, Qr, Qi, Cr, Ci, +1.0f, tid);
    {
        float* o1 = out + NTOT + (size_t)b * 65536 + d;
        o1[(size_t)tv0 * 128] = hsrc[i0] * (1.0f / 512.0f);
        o1[(size_t)tv1 * 128] = hsrc[i1] * (1.0f / 512.0f);
        o1[(size_t)tv2 * 128] = hsrc[i2] * (1.0f / 512.0f);
        o1[(size_t)tv3 * 128] = hsrc[i3] * (1.0f / 512.0f);
    }
    // ---- u1 output
    {
        float m0r = isT0 ? u1r0 : u1r3, m0i = isT0 ? u1i0 : u1i3;
        float m1r = isT0 ? u1r3 : u1r2, m1i = isT0 ? u1i3 : u1i2;
        float m2r = isT0 ? u1r2 : u1r1, m2i = isT0 ? u1i2 : u1i1;
        float m3r = isT0 ? u1r1 : u1r0, m3i = isT0 ? u1i1 : u1i0;
        float H0r = 0.5f * (u1r0 + m0r), H0i = 0.5f * (u1i0 - m0i);
        float H1r = 0.5f * (u1r1 + m1r), H1i = 0.5f * (u1i1 - m1i);
        float H2r = 0.5f * (u1r2 + m2r), H2i = 0.5f * (u1i2 - m2i);
        float H3r = 0.5f * (u1r3 + m3r), H3i = 0.5f * (u1i3 - m3i);
        if (g == 0) {
            Pr[i0] = H0r; Pi[i0] = H0i; Pr[i1] = H1r; Pi[i1] = H1i;
            Pr[i2] = H2r; Pi[i2] = H2i; Pr[i3] = H3r; Pi[i3] = H3i;
        } else {
            Qr[i0] = H0r; Qi[i0] = H0i; Qr[i1] = H1r; Qi[i1] = H1i;
            Qr[i2] = H2r; Qi[i2] = H2i; Qr[i3] = H3r; Qi[i3] = H3i;
        }
    }
    fft512_pack(Pr, Pi, Qr, Qi, Cr, Ci, +1.0f, tid);
    {
        float* o2 = out + 2 * (size_t)NTOT + (size_t)b * 65536 + d;
        o2[(size_t)tv0 * 128] = hsrc[i0] * (1.0f / 512.0f);
        o2[(size_t)tv1 * 128] = hsrc[i1] * (1.0f / 512.0f);
        o2[(size_t)tv2 * 128] = hsrc[i2] * (1.0f / 512.0f);
        o2[(size_t)tv3 * 128] = hsrc[i3] * (1.0f / 512.0f);
    }
}

// order[b]: argsort over K=2 of mean_d(omega). Stable: swap iff m1 < m0.
__global__ void order_kernel() {
    __shared__ float sm[64];
    int tid = threadIdx.x;
    if (tid < 64) {
        int b = tid >> 1, k = tid & 1;
        float s = 0.0f;
        for (int dd = 0; dd < 128; dd++)
            s += g_omega[((b << 7) + dd) * 2 + k];
        sm[tid] = s;
    }
    __syncthreads();
    if (tid < 32) g_swap[tid] = (sm[2 * tid + 1] < sm[2 * tid]) ? 1 : 0;
}

// zero x_trend; swap period/res segments where needed
__global__ void finalize_kernel(float* __restrict__ out) {
    int e = blockIdx.x * blockDim.x + threadIdx.x;
    if (e < NTOT) {
        out[e] = 0.0f;
        int b = e >> 16;
        if (g_swap[b]) {
            float a = out[NTOT + e];
            float c = out[2 * NTOT + e];
            out[NTOT + e] = c;
            out[2 * NTOT + e] = a;
        }
    }
}

extern "C" void kernel_launch(void* const* d_in, const int* in_sizes, int n_in,
                              void* d_out, int out_size) {
    const float* x = (const float*)d_in[0];
    float* out = (float*)d_out;
    vmd_main<<<NSIG / 2, NT>>>(x, out);
    order_kernel<<<1, 64>>>();
    finalize_kernel<<<(NTOT + 255) / 256, 256>>>(out);
}

// round 5
// speedup vs baseline: 1.1722x; 1.1722x over previous
#include <cuda_runtime.h>

#define L      512
#define NT     128
#define NSIG   4096
#define NTOT   (32*512*128)
// pad every 8 complex: conflict-free Stockham radix-8 (all indices affine, stride 72/9)
#define IDX(c) ((c) + ((c) >> 3))

__device__ float g_omega[NSIG * 2];
__device__ int   g_swap[32];

__device__ __forceinline__ float warpsum(float v) {
#pragma unroll
    for (int o = 16; o; o >>= 1) v += __shfl_xor_sync(0xffffffffu, v, o);
    return v;
}

struct C2 { float x, y; };
__device__ __forceinline__ C2 cadd(C2 a, C2 b) { return {a.x + b.x, a.y + b.y}; }
__device__ __forceinline__ C2 csub(C2 a, C2 b) { return {a.x - b.x, a.y - b.y}; }
__device__ __forceinline__ C2 cmul(C2 a, C2 b) {
    return {a.x * b.x - a.y * b.y, a.x * b.y + a.y * b.x};
}
__device__ __forceinline__ C2 cmuli(C2 a, float sgn) { return {-sgn * a.y, sgn * a.x}; }

// 8-point DFT butterfly, sign-parametrized (sgn=-1 fwd, +1 inv)
__device__ __forceinline__ void bfly8(const C2 c[8], C2 dd[8], float sgn) {
    const float S2 = 0.70710678118654752f;
    C2 t0 = cadd(c[0], c[4]), t1 = csub(c[0], c[4]);
    C2 t2 = cadd(c[2], c[6]), t3 = cmuli(csub(c[2], c[6]), sgn);
    C2 u0 = cadd(c[1], c[5]), u1 = csub(c[1], c[5]);
    C2 u2 = cadd(c[3], c[7]), u3 = cmuli(csub(c[3], c[7]), sgn);
    C2 E0 = cadd(t0, t2), E2 = csub(t0, t2);
    C2 E1 = cadd(t1, t3), E3 = csub(t1, t3);
    C2 O0 = cadd(u0, u2), O2 = csub(u0, u2);
    C2 O1 = cadd(u1, u3), O3 = csub(u1, u3);
    C2 w1c = { S2, sgn * S2};
    C2 w3c = {-S2, sgn * S2};
    C2 o1 = cmul(O1, w1c);
    C2 o2 = cmuli(O2, sgn);
    C2 o3 = cmul(O3, w3c);
    dd[0] = cadd(E0, O0); dd[4] = csub(E0, O0);
    dd[1] = cadd(E1, o1); dd[5] = csub(E1, o1);
    dd[2] = cadd(E2, o2); dd[6] = csub(E2, o2);
    dd[3] = cadd(E3, o3); dd[7] = csub(E3, o3);
}

// 512-pt Stockham radix-8 FFT, 3 stages, table twiddles (stored for INVERSE;
// sgn=-1 conjugates => forward). A -> B (A clobbered). NO 1/N scaling.
// First action is __syncthreads() (covers caller's writes to A); trailing sync.
__device__ __forceinline__ void fft3(const float2* __restrict__ tw0,
                                     const float2* __restrict__ tw1,
                                     float2* A, float2* B, float sgn, int tid) {
    __syncthreads();
    if (tid < 64) {                      // stage 0: A -> B
        const float2* ld = A + (tid + (tid >> 3));
        C2 c[8], dd[8];
#pragma unroll
        for (int q = 0; q < 8; q++) { float2 v = ld[72 * q]; c[q].x = v.x; c[q].y = v.y; }
        bfly8(c, dd, sgn);
        const float2* tp = tw0 + 7 * tid;
#pragma unroll
        for (int p = 1; p < 8; p++) {
            float2 w = tp[p - 1];
            C2 wc = {w.x, sgn * w.y};
            dd[p] = cmul(dd[p], wc);
        }
        float2* st = B + 9 * tid;
#pragma unroll
        for (int p = 0; p < 8; p++) st[p] = make_float2(dd[p].x, dd[p].y);
    }
    __syncthreads();
    if (tid < 64) {                      // stage 1: B -> A
        const int j = tid >> 3, k = tid & 7;
        const float2* ld = B + (k + 9 * j);
        C2 c[8], dd[8];
#pragma unroll
        for (int q = 0; q < 8; q++) { float2 v = ld[72 * q]; c[q].x = v.x; c[q].y = v.y; }
        bfly8(c, dd, sgn);
        const float2* tp = tw1 + 7 * j;
#pragma unroll
        for (int p = 1; p < 8; p++) {
            float2 w = tp[p - 1];
            C2 wc = {w.x, sgn * w.y};
            dd[p] = cmul(dd[p], wc);
        }
        float2* st = A + (k + 72 * j);
#pragma unroll
        for (int p = 0; p < 8; p++) st[9 * p] = make_float2(dd[p].x, dd[p].y);
    }
    __syncthreads();
    if (tid < 64) {                      // stage 2: A -> B, no twiddle
        const float2* ld = A + (tid + (tid >> 3));
        C2 c[8], dd[8];
#pragma unroll
        for (int q = 0; q < 8; q++) { float2 v = ld[72 * q]; c[q].x = v.x; c[q].y = v.y; }
        bfly8(c, dd, sgn);
        float2* st = B + (tid + (tid >> 3));
#pragma unroll
        for (int p = 0; p < 8; p++) st[72 * p] = make_float2(dd[p].x, dd[p].y);
    }
    __syncthreads();
}

// One CTA = one (b,d) signal. All spectra register-resident.
// Thread i>=1 owns bins {i, 256-i, 256+i, 512-i}; thread 0 owns {0,128,256,384}.
// Mirror (512-t)&511: slots (0<->3, 1<->2) general, (0<->0, 1<->3, 2<->2) for t0.
// Xor-256 (lambda shift): slots (0<->2, 1<->3) for everyone.
__global__ void __launch_bounds__(NT, 6) vmd_main(const float* __restrict__ x,
                                                  float* __restrict__ out) {
    __shared__ float2 A[576], B[576];
    __shared__ float2 tw0s[448], tw1s[56];
    __shared__ float red[32];

    const int tid = threadIdx.x;
    const int sig = blockIdx.x;
    const int b = sig >> 7, d = sig & 127;
    const float* xp = x + (size_t)b * 65536 + d;

    // build inverse twiddle tables: tw0[j*7+p-1]=e^{+2pi i j p/512}, j<64
    //                               tw1[j*7+p-1]=e^{+2pi i j p/64},  j<8
    for (int idx = tid; idx < 448 + 56; idx += NT) {
        if (idx < 448) {
            int j = idx / 7, pm = idx - 7 * j + 1;
            float ang = 6.283185307179586f * (float)(j * pm) * (1.0f / 512.0f);
            float sv, cv; sincosf(ang, &sv, &cv);
            tw0s[idx] = make_float2(cv, sv);
        } else {
            int r = idx - 448;
            int j = r / 7, pm = r - 7 * j + 1;
            float ang = 6.283185307179586f * (float)(j * pm) * (1.0f / 64.0f);
            float sv, cv; sincosf(ang, &sv, &cv);
            tw1s[r] = make_float2(cv, sv);
        }
    }

    const bool isT0 = (tid == 0);
    const int tv0 = isT0 ? 0   : tid;
    const int tv1 = isT0 ? 128 : 256 - tid;
    const int tv2 = isT0 ? 256 : 256 + tid;
    const int tv3 = isT0 ? 384 : 512 - tid;
    const int i0 = IDX(tv0), i1 = IDX(tv1), i2 = IDX(tv2), i3 = IDX(tv3);
    const float f0 = (float)tv0 * (1.0f / 512.0f);
    const float f1 = (float)tv1 * (1.0f / 512.0f);
    const float f2 = (float)(tv2 - 512) * (1.0f / 512.0f);
    const float f3 = (float)(tv3 - 512) * (1.0f / 512.0f);

    const float xs0 = xp[(size_t)tv0 * 128];
    const float xs1 = xp[(size_t)tv1 * 128];
    const float xs2 = xp[(size_t)tv2 * 128];
    const float xs3 = xp[(size_t)tv3 * 128];

    // forward FFT of x (conjugated table via sgn=-1)
    A[i0] = make_float2(xs0, 0.0f);
    A[i1] = make_float2(xs1, 0.0f);
    A[i2] = make_float2(xs2, 0.0f);
    A[i3] = make_float2(xs3, 0.0f);
    fft3(tw0s, tw1s, A, B, -1.0f, tid);
    float2 z;
    z = B[i0]; const float X0r = z.x, X0i = z.y;
    z = B[i1]; const float X1r = z.x, X1i = z.y;
    z = B[i2]; const float X2r = z.x, X2i = z.y;
    z = B[i3]; const float X3r = z.x, X3i = z.y;

    float u0r0, u0i0, u0r1, u0i1, u0r2, u0i2, u0r3, u0i3;
    float u1r0 = 0.f, u1i0 = 0.f, u1r1 = 0.f, u1i1 = 0.f;
    float u1r2 = 0.f, u1i2 = 0.f, u1r3 = 0.f, u1i3 = 0.f;
    float l0 = 0.f, l1 = 0.f, l2 = 0.f, l3 = 0.f;
    float om0 = 0.0f, om1 = 0.0f;

    for (int iter = 0; iter < 50; iter++) {
        // ---- Pass A: U0 = (X - Herm(U1) + lam'/2) / (1 + 2a(f-om0)^2)
        float m0r = isT0 ? u1r0 : u1r3, m0i = isT0 ? u1i0 : u1i3;
        float m1r = isT0 ? u1r3 : u1r2, m1i = isT0 ? u1i3 : u1i2;
        float m2r = isT0 ? u1r2 : u1r1, m2i = isT0 ? u1i2 : u1i1;
        float m3r = isT0 ? u1r1 : u1r0, m3i = isT0 ? u1i1 : u1i0;
        float h0r = 0.5f * (u1r0 + m0r), h0i = 0.5f * (u1i0 - m0i);
        float h1r = 0.5f * (u1r1 + m1r), h1i = 0.5f * (u1i1 - m1i);
        float h2r = 0.5f * (u1r2 + m2r), h2i = 0.5f * (u1i2 - m2i);
        float h3r = 0.5f * (u1r3 + m3r), h3i = 0.5f * (u1i3 - m3i);
        float df, q;
        df = f0 - om0; q = __frcp_rn(fmaf(1600.0f * df, df, 1.0f));
        u0r0 = (X0r - h0r + 0.5f * l2) * q; u0i0 = (X0i - h0i) * q;
        df = f1 - om0; q = __frcp_rn(fmaf(1600.0f * df, df, 1.0f));
        u0r1 = (X1r - h1r + 0.5f * l3) * q; u0i1 = (X1i - h1i) * q;
        df = f2 - om0; q = __frcp_rn(fmaf(1600.0f * df, df, 1.0f));
        u0r2 = (X2r - h2r + 0.5f * l0) * q; u0i2 = (X2i - h2i) * q;
        df = f3 - om0; q = __frcp_rn(fmaf(1600.0f * df, df, 1.0f));
        u0r3 = (X3r - h3r + 0.5f * l1) * q; u0i3 = (X3i - h3i) * q;

        // ---- Pass B: h = Herm(U0); omega0 sums (f>=0 slots 0,1); U1 update
        m0r = isT0 ? u0r0 : u0r3; m0i = isT0 ? u0i0 : u0i3;
        m1r = isT0 ? u0r3 : u0r2; m1i = isT0 ? u0i3 : u0i2;
        m2r = isT0 ? u0r2 : u0r1; m2i = isT0 ? u0i2 : u0i1;
        m3r = isT0 ? u0r1 : u0r0; m3i = isT0 ? u0i1 : u0i0;
        h0r = 0.5f * (u0r0 + m0r); h0i = 0.5f * (u0i0 - m0i);
        h1r = 0.5f * (u0r1 + m1r); h1i = 0.5f * (u0i1 - m1i);
        h2r = 0.5f * (u0r2 + m2r); h2i = 0.5f * (u0i2 - m2i);
        h3r = 0.5f * (u0r3 + m3r); h3i = 0.5f * (u0i3 - m3i);
        float p0 = h0r * h0r + h0i * h0i;
        float p1 = h1r * h1r + h1i * h1i;
        float n0 = f0 * p0 + f1 * p1, den0 = p0 + p1;
        df = f0 - om1; q = __frcp_rn(fmaf(1600.0f * df, df, 1.0f));
        u1r0 = (X0r - h0r + 0.5f * l2) * q; u1i0 = (X0i - h0i) * q;
        df = f1 - om1; q = __frcp_rn(fmaf(1600.0f * df, df, 1.0f));
        u1r1 = (X1r - h1r + 0.5f * l3) * q; u1i1 = (X1i - h1i) * q;
        df = f2 - om1; q = __frcp_rn(fmaf(1600.0f * df, df, 1.0f));
        u1r2 = (X2r - h2r + 0.5f * l0) * q; u1i2 = (X2i - h2i) * q;
        df = f3 - om1; q = __frcp_rn(fmaf(1600.0f * df, df, 1.0f));
        u1r3 = (X3r - h3r + 0.5f * l1) * q; u1i3 = (X3i - h3i) * q;

        // ---- Pass C: omega1 sums from Herm(U1); scatter V = U0+U1
        m0r = isT0 ? u1r0 : u1r3; m0i = isT0 ? u1i0 : u1i3;
        m1r = isT0 ? u1r3 : u1r2; m1i = isT0 ? u1i3 : u1i2;
        h0r = 0.5f * (u1r0 + m0r); h0i = 0.5f * (u1i0 - m0i);
        h1r = 0.5f * (u1r1 + m1r); h1i = 0.5f * (u1i1 - m1i);
        p0 = h0r * h0r + h0i * h0i;
        p1 = h1r * h1r + h1i * h1i;
        float n1 = f0 * p0 + f1 * p1, den1 = p0 + p1;

        A[i0] = make_float2(u0r0 + u1r0, u0i0 + u1i0);
        A[i1] = make_float2(u0r1 + u1r1, u0i1 + u1i1);
        A[i2] = make_float2(u0r2 + u1r2, u0i2 + u1i2);
        A[i3] = make_float2(u0r3 + u1r3, u0i3 + u1i3);

        // block reduction, parity double-buffered (no extra barrier needed)
        n0 = warpsum(n0); den0 = warpsum(den0);
        n1 = warpsum(n1); den1 = warpsum(den1);
        {
            int po = (iter & 1) << 4;
            int w = tid >> 5;
            if ((tid & 31) == 0) {
                red[po + w] = n0;      red[po + 4 + w] = den0;
                red[po + 8 + w] = n1;  red[po + 12 + w] = den1;
            }
        }
        fft3(tw0s, tw1s, A, B, +1.0f, tid);   // inverse (unscaled) of U0+U1
        {
            int po = (iter & 1) << 4;
            om0 = (red[po + 0] + red[po + 1] + red[po + 2] + red[po + 3]) /
                  (red[po + 4] + red[po + 5] + red[po + 6] + red[po + 7] + 1e-7f);
            om1 = (red[po + 8] + red[po + 9] + red[po + 10] + red[po + 11]) /
                  (red[po + 12] + red[po + 13] + red[po + 14] + red[po + 15] + 1e-7f);
        }
        // lam += tau * (x - real(ifft(U0+U1))/512)
        l0 = fmaf(0.001f, xs0 - B[i0].x * (1.0f / 512.0f), l0);
        l1 = fmaf(0.001f, xs1 - B[i1].x * (1.0f / 512.0f), l1);
        l2 = fmaf(0.001f, xs2 - B[i2].x * (1.0f / 512.0f), l2);
        l3 = fmaf(0.001f, xs3 - B[i3].x * (1.0f / 512.0f), l3);
    }

    if (tid == 0) {
        g_omega[sig * 2 + 0] = om0;
        g_omega[sig * 2 + 1] = om1;
    }

    // u0 time-domain -> out[NTOT + ...]
    A[i0] = make_float2(u0r0, u0i0);
    A[i1] = make_float2(u0r1, u0i1);
    A[i2] = make_float2(u0r2, u0i2);
    A[i3] = make_float2(u0r3, u0i3);
    fft3(tw0s, tw1s, A, B, +1.0f, tid);
    {
        float* o1 = out + NTOT + (size_t)b * 65536 + d;
        o1[(size_t)tv0 * 128] = B[i0].x * (1.0f / 512.0f);
        o1[(size_t)tv1 * 128] = B[i1].x * (1.0f / 512.0f);
        o1[(size_t)tv2 * 128] = B[i2].x * (1.0f / 512.0f);
        o1[(size_t)tv3 * 128] = B[i3].x * (1.0f / 512.0f);
    }
    // u1 time-domain -> out[2*NTOT + ...]
    A[i0] = make_float2(u1r0, u1i0);
    A[i1] = make_float2(u1r1, u1i1);
    A[i2] = make_float2(u1r2, u1i2);
    A[i3] = make_float2(u1r3, u1i3);
    fft3(tw0s, tw1s, A, B, +1.0f, tid);
    {
        float* o2 = out + 2 * (size_t)NTOT + (size_t)b * 65536 + d;
        o2[(size_t)tv0 * 128] = B[i0].x * (1.0f / 512.0f);
        o2[(size_t)tv1 * 128] = B[i1].x * (1.0f / 512.0f);
        o2[(size_t)tv2 * 128] = B[i2].x * (1.0f / 512.0f);
        o2[(size_t)tv3 * 128] = B[i3].x * (1.0f / 512.0f);
    }
}

// order[b]: argsort over K=2 of mean_d(omega). Stable: swap iff m1 < m0.
__global__ void order_kernel() {
    __shared__ float sm[64];
    int tid = threadIdx.x;
    if (tid < 64) {
        int b = tid >> 1, k = tid & 1;
        float s = 0.0f;
        for (int dd = 0; dd < 128; dd++)
            s += g_omega[((b << 7) + dd) * 2 + k];
        sm[tid] = s;
    }
    __syncthreads();
    if (tid < 32) g_swap[tid] = (sm[2 * tid + 1] < sm[2 * tid]) ? 1 : 0;
}

// zero x_trend; swap period/res segments where needed
__global__ void finalize_kernel(float* __restrict__ out) {
    int e = blockIdx.x * blockDim.x + threadIdx.x;
    if (e < NTOT) {
        out[e] = 0.0f;
        int b = e >> 16;
        if (g_swap[b]) {
            float a = out[NTOT + e];
            float c = out[2 * NTOT + e];
            out[NTOT + e] = c;
            out[2 * NTOT + e] = a;
        }
    }
}

extern "C" void kernel_launch(void* const* d_in, const int* in_sizes, int n_in,
                              void* d_out, int out_size) {
    const float* x = (const float*)d_in[0];
    float* out = (float*)d_out;
    vmd_main<<<NSIG, NT>>>(x, out);
    order_kernel<<<1, 64>>>();
    finalize_kernel<<<(NTOT + 255) / 256, 256>>>(out);
}

// round 6
// speedup vs baseline: 1.3642x; 1.1638x over previous
#include <cuda_runtime.h>

#define L      512
#define NT     128
#define NSIG   4096
#define NTOT   (32*512*128)

__device__ float g_omega[NSIG * 2];
__device__ int   g_swap[32];

__device__ __forceinline__ float warpsum(float v) {
#pragma unroll
    for (int o = 16; o; o >>= 1) v += __shfl_xor_sync(0xffffffffu, v, o);
    return v;
}

struct C2 { float x, y; };
__device__ __forceinline__ C2 cadd(C2 a, C2 b) { return {a.x + b.x, a.y + b.y}; }
__device__ __forceinline__ C2 csub(C2 a, C2 b) { return {a.x - b.x, a.y - b.y}; }
__device__ __forceinline__ C2 cmul(C2 a, C2 b) {
    return {a.x * b.x - a.y * b.y, a.x * b.y + a.y * b.x};
}
__device__ __forceinline__ C2 cmuli(C2 a, float sgn) { return {-sgn * a.y, sgn * a.x}; }

__device__ __forceinline__ void bfly8(const C2 c[8], C2 dd[8], float sgn) {
    const float S2 = 0.70710678118654752f;
    C2 t0 = cadd(c[0], c[4]), t1 = csub(c[0], c[4]);
    C2 t2 = cadd(c[2], c[6]), t3 = cmuli(csub(c[2], c[6]), sgn);
    C2 u0 = cadd(c[1], c[5]), u1 = csub(c[1], c[5]);
    C2 u2 = cadd(c[3], c[7]), u3 = cmuli(csub(c[3], c[7]), sgn);
    C2 E0 = cadd(t0, t2), E2 = csub(t0, t2);
    C2 E1 = cadd(t1, t3), E3 = csub(t1, t3);
    C2 O0 = cadd(u0, u2), O2 = csub(u0, u2);
    C2 O1 = cadd(u1, u3), O3 = csub(u1, u3);
    C2 w1c = { S2, sgn * S2};
    C2 w3c = {-S2, sgn * S2};
    C2 o1 = cmul(O1, w1c);
    C2 o2 = cmuli(O2, sgn);
    C2 o3 = cmul(O3, w3c);
    dd[0] = cadd(E0, O0); dd[4] = csub(E0, O0);
    dd[1] = cadd(E1, o1); dd[5] = csub(E1, o1);
    dd[2] = cadd(E2, o2); dd[6] = csub(E2, o2);
    dd[3] = cadd(E3, o3); dd[7] = csub(E3, o3);
}

// 256-pt Stockham FFT, radices (8,8,4). X0 -> X1 -> X2 -> X3.
// X0/X3 natural layout; X1 XOR-swizzled (l ^ ((l>>4)&7)); X2 padded (l + 8*(l>>6)).
// All LDS/STS conflict-free (mod-16 distinct per half-warp).
// Tables stored for INVERSE twiddles; sgn=-1 conjugates => forward. No 1/N scaling.
// First action is __syncthreads() (covers caller's writes to X0); trailing sync.
__device__ __forceinline__ void fft256(float2* X0, float2* X1, float2* X2, float2* X3,
                                       const float2* tw0, const float2* tw1,
                                       float sgn, int tid) {
    __syncthreads();
    if (tid < 32) {                 // stage 0: radix-8, X0 -> X1
        const int j = tid;
        C2 c[8], dd[8];
#pragma unroll
        for (int q = 0; q < 8; q++) { float2 v = X0[j + 32 * q]; c[q].x = v.x; c[q].y = v.y; }
        bfly8(c, dd, sgn);
        const float2* tp = tw0 + 7 * j;
#pragma unroll
        for (int p = 1; p < 8; p++) {
            float2 w = tp[p - 1];
            C2 wc = {w.x, sgn * w.y};
            dd[p] = cmul(dd[p], wc);
        }
        const int s = (j >> 1) & 7;
        float2* st = X1 + 8 * j;
#pragma unroll
        for (int p = 0; p < 8; p++) st[p ^ s] = make_float2(dd[p].x, dd[p].y);
    }
    __syncthreads();
    if (tid < 32) {                 // stage 1: radix-8, X1 -> X2
        const int j = tid >> 3, k = tid & 7;
        C2 c[8], dd[8];
#pragma unroll
        for (int q = 0; q < 8; q++) {
            int l = tid + 32 * q;
            float2 v = X1[l ^ ((l >> 4) & 7)];
            c[q].x = v.x; c[q].y = v.y;
        }
        bfly8(c, dd, sgn);
        const float2* tp = tw1 + 7 * j;
#pragma unroll
        for (int p = 1; p < 8; p++) {
            float2 w = tp[p - 1];
            C2 wc = {w.x, sgn * w.y};
            dd[p] = cmul(dd[p], wc);
        }
        float2* st = X2 + (k + 72 * j);
#pragma unroll
        for (int p = 0; p < 8; p++) st[8 * p] = make_float2(dd[p].x, dd[p].y);
    }
    __syncthreads();
    if (tid < 64) {                 // stage 2: radix-4, X2 -> X3 (no twiddle)
        const int k = tid;
        C2 c[4];
#pragma unroll
        for (int q = 0; q < 4; q++) { float2 v = X2[k + 72 * q]; c[q].x = v.x; c[q].y = v.y; }
        C2 t0 = cadd(c[0], c[2]), t1 = csub(c[0], c[2]);
        C2 t2 = cadd(c[1], c[3]), t3 = cmuli(csub(c[1], c[3]), sgn);
        C2 d0 = cadd(t0, t2), d2 = csub(t0, t2);
        C2 d1 = cadd(t1, t3), d3 = csub(t1, t3);
        X3[k]       = make_float2(d0.x, d0.y);
        X3[k + 64]  = make_float2(d1.x, d1.y);
        X3[k + 128] = make_float2(d2.x, d2.y);
        X3[k + 192] = make_float2(d3.x, d3.y);
    }
    __syncthreads();
}

// One CTA = one (b,d) signal. Spectra register-resident; thread wt owns bins
// {wt, 256-wt, 256+wt, 512-wt} (wt=0: {0,128,256,384}). All length-512
// transforms done as 256-pt complex FFTs via real-signal packing; the
// (k, k+256) pairing needed by the packing is slots (0,2)/(1,3) of ONE thread.
__global__ void __launch_bounds__(NT, 6) vmd_main(const float* __restrict__ x,
                                                  float* __restrict__ out) {
    __shared__ float2 X0[256], X1[256], X2[280], X3[256];
    __shared__ float2 tw0s[224], tw1s[28];
    __shared__ float red[32];

    const int tid = threadIdx.x;
    const int sig = blockIdx.x;
    const int b = sig >> 7, d = sig & 127;
    const float* xp = x + (size_t)b * 65536 + d;

    // inverse twiddle tables: tw0[7j+p-1]=cis(2pi j p/256) j<32; tw1: /32, j<4
    for (int idx = tid; idx < 224 + 28; idx += NT) {
        if (idx < 224) {
            int j = idx / 7, pm = idx - 7 * j + 1;
            float sv, cv;
            sincosf(6.283185307179586f * (float)(j * pm) * (1.0f / 256.0f), &sv, &cv);
            tw0s[idx] = make_float2(cv, sv);
        } else {
            int r = idx - 224;
            int j = r / 7, pm = r - 7 * j + 1;
            float sv, cv;
            sincosf(6.283185307179586f * (float)(j * pm) * (1.0f / 32.0f), &sv, &cv);
            tw1s[r] = make_float2(cv, sv);
        }
    }

    const bool isT0 = (tid == 0);
    const int tv0 = isT0 ? 0   : tid;
    const int tv1 = isT0 ? 128 : 256 - tid;
    const int tv2 = isT0 ? 256 : 256 + tid;
    const int tv3 = isT0 ? 384 : 512 - tid;
    const float f0 = (float)tv0 * (1.0f / 512.0f);
    const float f1 = (float)tv1 * (1.0f / 512.0f);
    const float f2 = (float)(tv2 - 512) * (1.0f / 512.0f);
    const float f3 = (float)(tv3 - 512) * (1.0f / 512.0f);
    const int k1 = tv0;            // packs slots (0,2)
    const int k2 = tv1 & 255;      // packs slots (1,3)
    const int g0 = tv0 >> 1, g1 = tv1 >> 1, g2 = tv2 >> 1, g3 = tv3 >> 1;
    const int odd = tv0 & 1;       // parity shared by all four tv's
    // wA = cis(2pi k1/512), wB = cis(2pi k2/512)  (k2 = tv1 incl. t=0 case)
    float wAr, wAi, wBr, wBi;
    sincosf(6.283185307179586f * f0, &wAi, &wAr);
    sincosf(6.283185307179586f * f1, &wBi, &wBr);

    const float xs0 = xp[(size_t)tv0 * 128];
    const float xs1 = xp[(size_t)tv1 * 128];
    const float xs2 = xp[(size_t)tv2 * 128];
    const float xs3 = xp[(size_t)tv3 * 128];

    // forward: pack z[m] = x[2m] + i x[2m+1], one 256-pt forward FFT
#pragma unroll
    for (int m = tid; m < 256; m += NT) {
        float ev = xp[(size_t)(2 * m) * 128];
        float ov = xp[(size_t)(2 * m + 1) * 128];
        X0[m] = make_float2(ev, ov);
    }
    fft256(X0, X1, X2, X3, tw0s, tw1s, -1.0f, tid);
    // unpack Z -> X[tv0..tv3]
    float X0r, X0i, X1r, X1i, X2r, X2i, X3r, X3i;
    {
        float2 Zt = X3[k1], Zk = X3[k2];
        float2 M1 = isT0 ? Zt : Zk;   // mirror of k1
        float2 M2 = isT0 ? Zk : Zt;   // mirror of k2
        float Er = 0.5f * (Zt.x + M1.x), Ei = 0.5f * (Zt.y - M1.y);
        float Dr = Zt.x - M1.x,         Di = Zt.y + M1.y;
        float Or = 0.5f * Di,           Oi = -0.5f * Dr;          // -i*D/2
        float cr = wAr * Or + wAi * Oi, ci = wAr * Oi - wAi * Or; // conj(wA)*O
        X0r = Er + cr; X0i = Ei + ci;
        X2r = Er - cr; X2i = Ei - ci;
        float Er2 = 0.5f * (Zk.x + M2.x), Ei2 = 0.5f * (Zk.y - M2.y);
        float Dr2 = Zk.x - M2.x,          Di2 = Zk.y + M2.y;
        float Or2 = 0.5f * Di2,           Oi2 = -0.5f * Dr2;
        float cr2 = wBr * Or2 + wBi * Oi2, ci2 = wBr * Oi2 - wBi * Or2;
        X1r = Er2 + cr2; X1i = Ei2 + ci2;
        X3r = Er2 - cr2; X3i = Ei2 - ci2;
    }

    float u0r0, u0i0, u0r1, u0i1, u0r2, u0i2, u0r3, u0i3;
    float u1r0 = 0.f, u1i0 = 0.f, u1r1 = 0.f, u1i1 = 0.f;
    float u1r2 = 0.f, u1i2 = 0.f, u1r3 = 0.f, u1i3 = 0.f;
    float l0 = 0.f, l1 = 0.f, l2 = 0.f, l3 = 0.f;
    float om0 = 0.0f, om1 = 0.0f;
    const float* z3f = reinterpret_cast<const float*>(X3);

    for (int iter = 0; iter < 50; iter++) {
        // ---- Pass A: U0 = (X - Herm(U1) + lam'/2) / (1 + 2a(f-om0)^2)
        float m0r = isT0 ? u1r0 : u1r3, m0i = isT0 ? u1i0 : u1i3;
        float m1r = isT0 ? u1r3 : u1r2, m1i = isT0 ? u1i3 : u1i2;
        float m2r = isT0 ? u1r2 : u1r1, m2i = isT0 ? u1i2 : u1i1;
        float m3r = isT0 ? u1r1 : u1r0, m3i = isT0 ? u1i1 : u1i0;
        float h0r = 0.5f * (u1r0 + m0r), h0i = 0.5f * (u1i0 - m0i);
        float h1r = 0.5f * (u1r1 + m1r), h1i = 0.5f * (u1i1 - m1i);
        float h2r = 0.5f * (u1r2 + m2r), h2i = 0.5f * (u1i2 - m2i);
        float h3r = 0.5f * (u1r3 + m3r), h3i = 0.5f * (u1i3 - m3i);
        float df, q;
        df = f0 - om0; q = __frcp_rn(fmaf(1600.0f * df, df, 1.0f));
        u0r0 = (X0r - h0r + 0.5f * l2) * q; u0i0 = (X0i - h0i) * q;
        df = f1 - om0; q = __frcp_rn(fmaf(1600.0f * df, df, 1.0f));
        u0r1 = (X1r - h1r + 0.5f * l3) * q; u0i1 = (X1i - h1i) * q;
        df = f2 - om0; q = __frcp_rn(fmaf(1600.0f * df, df, 1.0f));
        u0r2 = (X2r - h2r + 0.5f * l0) * q; u0i2 = (X2i - h2i) * q;
        df = f3 - om0; q = __frcp_rn(fmaf(1600.0f * df, df, 1.0f));
        u0r3 = (X3r - h3r + 0.5f * l1) * q; u0i3 = (X3i - h3i) * q;

        // ---- Pass B: h = Herm(U0) (kept live); omega0 sums; U1 update
        m0r = isT0 ? u0r0 : u0r3; m0i = isT0 ? u0i0 : u0i3;
        m1r = isT0 ? u0r3 : u0r2; m1i = isT0 ? u0i3 : u0i2;
        m2r = isT0 ? u0r2 : u0r1; m2i = isT0 ? u0i2 : u0i1;
        m3r = isT0 ? u0r1 : u0r0; m3i = isT0 ? u0i1 : u0i0;
        h0r = 0.5f * (u0r0 + m0r); h0i = 0.5f * (u0i0 - m0i);
        h1r = 0.5f * (u0r1 + m1r); h1i = 0.5f * (u0i1 - m1i);
        h2r = 0.5f * (u0r2 + m2r); h2i = 0.5f * (u0i2 - m2i);
        h3r = 0.5f * (u0r3 + m3r); h3i = 0.5f * (u0i3 - m3i);
        float p0 = h0r * h0r + h0i * h0i;
        float p1 = h1r * h1r + h1i * h1i;
        float n0 = f0 * p0 + f1 * p1, den0 = p0 + p1;
        df = f0 - om1; q = __frcp_rn(fmaf(1600.0f * df, df, 1.0f));
        u1r0 = (X0r - h0r + 0.5f * l2) * q; u1i0 = (X0i - h0i) * q;
        df = f1 - om1; q = __frcp_rn(fmaf(1600.0f * df, df, 1.0f));
        u1r1 = (X1r - h1r + 0.5f * l3) * q; u1i1 = (X1i - h1i) * q;
        df = f2 - om1; q = __frcp_rn(fmaf(1600.0f * df, df, 1.0f));
        u1r2 = (X2r - h2r + 0.5f * l0) * q; u1i2 = (X2i - h2i) * q;
        df = f3 - om1; q = __frcp_rn(fmaf(1600.0f * df, df, 1.0f));
        u1r3 = (X3r - h3r + 0.5f * l1) * q; u1i3 = (X3i - h3i) * q;

        // ---- Pass C: kx = Herm(U1); omega1 sums; H = h + kx; pack & scatter
        m0r = isT0 ? u1r0 : u1r3; m0i = isT0 ? u1i0 : u1i3;
        m1r = isT0 ? u1r3 : u1r2; m1i = isT0 ? u1i3 : u1i2;
        m2r = isT0 ? u1r2 : u1r1; m2i = isT0 ? u1i2 : u1i1;
        m3r = isT0 ? u1r1 : u1r0; m3i = isT0 ? u1i1 : u1i0;
        float k0r = 0.5f * (u1r0 + m0r), k0i = 0.5f * (u1i0 - m0i);
        float k1r = 0.5f * (u1r1 + m1r), k1i = 0.5f * (u1i1 - m1i);
        float k2r = 0.5f * (u1r2 + m2r), k2i = 0.5f * (u1i2 - m2i);
        float k3r = 0.5f * (u1r3 + m3r), k3i = 0.5f * (u1i3 - m3i);
        p0 = k0r * k0r + k0i * k0i;
        p1 = k1r * k1r + k1i * k1i;
        float n1 = f0 * p0 + f1 * p1, den1 = p0 + p1;
        float H0r = h0r + k0r, H0i = h0i + k0i;
        float H1r = h1r + k1r, H1i = h1i + k1i;
        float H2r = h2r + k2r, H2i = h2i + k2i;
        float H3r = h3r + k3r, H3i = h3i + k3i;
        // In[k1] = (H0+H2) + i*((H0-H2)*wA) ; In[k2] = (H1+H3) + i*((H1-H3)*wB)
        {
            float E1r = H0r + H2r, E1i = H0i + H2i;
            float D1r = H0r - H2r, D1i = H0i - H2i;
            float O1r = D1r * wAr - D1i * wAi, O1i = D1r * wAi + D1i * wAr;
            X0[k1] = make_float2(E1r - O1i, E1i + O1r);
            float E2r = H1r + H3r, E2i = H1i + H3i;
            float D2r = H1r - H3r, D2i = H1i - H3i;
            float O2r = D2r * wBr - D2i * wBi, O2i = D2r * wBi + D2i * wBr;
            X0[k2] = make_float2(E2r - O2i, E2i + O2r);
        }

        // block reduction, parity double-buffered
        n0 = warpsum(n0); den0 = warpsum(den0);
        n1 = warpsum(n1); den1 = warpsum(den1);
        {
            int po = (iter & 1) << 4;
            int w = tid >> 5;
            if ((tid & 31) == 0) {
                red[po + w] = n0;      red[po + 4 + w] = den0;
                red[po + 8 + w] = n1;  red[po + 12 + w] = den1;
            }
        }
        fft256(X0, X1, X2, X3, tw0s, tw1s, +1.0f, tid);   // ifft -> z in X3
        {
            int po = (iter & 1) << 4;
            om0 = (red[po + 0] + red[po + 1] + red[po + 2] + red[po + 3]) /
                  (red[po + 4] + red[po + 5] + red[po + 6] + red[po + 7] + 1e-7f);
            om1 = (red[po + 8] + red[po + 9] + red[po + 10] + red[po + 11]) /
                  (red[po + 12] + red[po + 13] + red[po + 14] + red[po + 15] + 1e-7f);
        }
        // lam += tau*(x - h/512);  h[tv] = z[tv>>1].{x|y} by parity
        l0 = fmaf(0.001f, xs0 - z3f[2 * g0 + odd] * (1.0f / 512.0f), l0);
        l1 = fmaf(0.001f, xs1 - z3f[2 * g1 + odd] * (1.0f / 512.0f), l1);
        l2 = fmaf(0.001f, xs2 - z3f[2 * g2 + odd] * (1.0f / 512.0f), l2);
        l3 = fmaf(0.001f, xs3 - z3f[2 * g3 + odd] * (1.0f / 512.0f), l3);
    }

    if (tid == 0) {
        g_omega[sig * 2 + 0] = om0;
        g_omega[sig * 2 + 1] = om1;
    }

    // ---- outputs: for U in {U0, U1}: pack Herm(U), one ifft256, gather, store
#pragma unroll 1
    for (int which = 0; which < 2; which++) {
        float ur0 = which ? u1r0 : u0r0, ui0 = which ? u1i0 : u0i0;
        float ur1 = which ? u1r1 : u0r1, ui1 = which ? u1i1 : u0i1;
        float ur2 = which ? u1r2 : u0r2, ui2 = which ? u1i2 : u0i2;
        float ur3 = which ? u1r3 : u0r3, ui3 = which ? u1i3 : u0i3;
        float m0r = isT0 ? ur0 : ur3, m0i = isT0 ? ui0 : ui3;
        float m1r = isT0 ? ur3 : ur2, m1i = isT0 ? ui3 : ui2;
        float m2r = isT0 ? ur2 : ur1, m2i = isT0 ? ui2 : ui1;
        float m3r = isT0 ? ur1 : ur0, m3i = isT0 ? ui1 : ui0;
        float H0r = 0.5f * (ur0 + m0r), H0i = 0.5f * (ui0 - m0i);
        float H1r = 0.5f * (ur1 + m1r), H1i = 0.5f * (ui1 - m1i);
        float H2r = 0.5f * (ur2 + m2r), H2i = 0.5f * (ui2 - m2i);
        float H3r = 0.5f * (ur3 + m3r), H3i = 0.5f * (ui3 - m3i);
        float E1r = H0r + H2r, E1i = H0i + H2i;
        float D1r = H0r - H2r, D1i = H0i - H2i;
        float O1r = D1r * wAr - D1i * wAi, O1i = D1r * wAi + D1i * wAr;
        X0[k1] = make_float2(E1r - O1i, E1i + O1r);
        float E2r = H1r + H3r, E2i = H1i + H3i;
        float D2r = H1r - H3r, D2i = H1i - H3i;
        float O2r = D2r * wBr - D2i * wBi, O2i = D2r * wBi + D2i * wBr;
        X0[k2] = make_float2(E2r - O2i, E2i + O2r);
        fft256(X0, X1, X2, X3, tw0s, tw1s, +1.0f, tid);
        float* o = out + (size_t)(which + 1) * NTOT + (size_t)b * 65536 + d;
        o[(size_t)tv0 * 128] = z3f[2 * g0 + odd] * (1.0f / 512.0f);
        o[(size_t)tv1 * 128] = z3f[2 * g1 + odd] * (1.0f / 512.0f);
        o[(size_t)tv2 * 128] = z3f[2 * g2 + odd] * (1.0f / 512.0f);
        o[(size_t)tv3 * 128] = z3f[2 * g3 + odd] * (1.0f / 512.0f);
    }
}

// order[b]: argsort over K=2 of mean_d(omega). Stable: swap iff m1 < m0.
__global__ void order_kernel() {
    __shared__ float sm[64];
    int tid = threadIdx.x;
    if (tid < 64) {
        int b = tid >> 1, k = tid & 1;
        float s = 0.0f;
        for (int dd = 0; dd < 128; dd++)
            s += g_omega[((b << 7) + dd) * 2 + k];
        sm[tid] = s;
    }
    __syncthreads();
    if (tid < 32) g_swap[tid] = (sm[2 * tid + 1] < sm[2 * tid]) ? 1 : 0;
}

// zero x_trend; swap period/res segments where needed
__global__ void finalize_kernel(float* __restrict__ out) {
    int e = blockIdx.x * blockDim.x + threadIdx.x;
    if (e < NTOT) {
        out[e] = 0.0f;
        int b = e >> 16;
        if (g_swap[b]) {
            float a = out[NTOT + e];
            float c = out[2 * NTOT + e];
            out[NTOT + e] = c;
            out[2 * NTOT + e] = a;
        }
    }
}

extern "C" void kernel_launch(void* const* d_in, const int* in_sizes, int n_in,
                              void* d_out, int out_size) {
    const float* x = (const float*)d_in[0];
    float* out = (float*)d_out;
    vmd_main<<<NSIG, NT>>>(x, out);
    order_kernel<<<1, 64>>>();
    finalize_kernel<<<(NTOT + 255) / 256, 256>>>(out);
}